// round 11
// baseline (speedup 1.0000x reference)
#include <cuda_runtime.h>
#include <cuda_fp16.h>
#include <mma.h>

using namespace nvcuda;

#define BATCH 8
#define SEQ   2048
#define DIM   1024
#define MTOT  (BATCH * SEQ)

// ---------------------------------------------------------------------------
// Device scratch (bss — no runtime allocation)
// ---------------------------------------------------------------------------
__device__ __half g_xh [(size_t)MTOT * DIM];        // x (fp16)
__device__ __half g_qh [(size_t)MTOT * DIM];        // Q (fp16)
__device__ __half g_kh [(size_t)MTOT * DIM];        // K (fp16)
__device__ __half g_vth[(size_t)MTOT * DIM];        // V^T per batch [DIM][SEQ]
__device__ float  g_s  [(size_t)BATCH * SEQ * SEQ]; // scores (fp32)
__device__ __half g_p  [(size_t)BATCH * SEQ * SEQ]; // probs (fp16)
__device__ __half g_wqT[(size_t)DIM * DIM];         // W^T [DOUT][DIN] fp16
__device__ __half g_wkT[(size_t)DIM * DIM];
__device__ __half g_wvT[(size_t)DIM * DIM];

// ---------------------------------------------------------------------------
// cp.async helper (16B)
// ---------------------------------------------------------------------------
__device__ __forceinline__ void cp16(void* dst, const void* src) {
    unsigned sdst = (unsigned)__cvta_generic_to_shared(dst);
    asm volatile("cp.async.cg.shared.global [%0], [%1], 16;" :: "r"(sdst), "l"(src));
}
#define CP_COMMIT() asm volatile("cp.async.commit_group;")

// ---------------------------------------------------------------------------
// fp16 GEMM: C[256,128] = A[256,K] @ B[128,K]^T, fp32 accumulate.
// 256 threads = 8 warps (4m x 2n); warp tile 64x64 = 4x4 m16n16k16 frags.
// Crossbar model per K32 chunk: frag LDS 64KB (512 cyc) + cp 24KB (192) vs
// 1M MACs (512 tensor-cyc) -> tensor ceiling ~73% (R10 config was 50%).
// BK=32, 3-stage cp.async pipeline, one barrier per chunk. SMEM 92160B.
// OUT_MODE: 0 = fp32 direct, 1 = fp16 (staged convert), 2 = fp16 transposed.
// ---------------------------------------------------------------------------
#define BK        32
#define TSTRIDE   40                        // halves per row (80B)
#define A_CH      (256 * TSTRIDE)           // A chunk halves (20480B)
#define B_CH      (128 * TSTRIDE)           // B chunk halves (10240B)
#define STAGE_H   (A_CH + B_CH)
#define SMEM_DYN  (3 * STAGE_H * 2)         // 92160B

template <int OUT_MODE>
__device__ __forceinline__ void gemm_body(const __half* __restrict__ A,
                                          const __half* __restrict__ B,
                                          void* __restrict__ Cout,
                                          int lda, int ldb, int ldc, int kIters)
{
    extern __shared__ __align__(16) unsigned char dynraw[];
    __half* pool = (__half*)dynraw;

    const int tid  = threadIdx.x;               // 0..255
    const int wid  = tid >> 5;                  // 0..7
    const int lane = tid & 31;
    const int wm   = wid >> 1;                  // 0..3  (64-row slab of 256)
    const int wn   = wid & 1;                   // 0..1  (64-col slab of 128)

    wmma::fragment<wmma::accumulator, 16, 16, 16, float> acc[4][4];
#pragma unroll
    for (int i = 0; i < 4; i++)
#pragma unroll
        for (int j = 0; j < 4; j++) wmma::fill_fragment(acc[i][j], 0.0f);

    auto load_chunk = [&](int kt) {
        __half* Ad = pool + (kt % 3) * STAGE_H;
        __half* Bd = Ad + A_CH;
#pragma unroll
        for (int u = 0; u < 4; u++) {            // A: 256 rows x 32 halves
            int idx = u * 256 + tid;             // 0..1023
            int row = idx >> 2;                  // 0..255
            int c8  = (idx & 3) * 8;
            cp16(Ad + row * TSTRIDE + c8, A + (size_t)row * lda + kt * BK + c8);
        }
#pragma unroll
        for (int u = 0; u < 2; u++) {            // B: 128 rows x 32 halves
            int idx = u * 256 + tid;             // 0..511
            int row = idx >> 2;                  // 0..127
            int c8  = (idx & 3) * 8;
            cp16(Bd + row * TSTRIDE + c8, B + (size_t)row * ldb + kt * BK + c8);
        }
        CP_COMMIT();
    };

    load_chunk(0);
    if (kIters > 1) load_chunk(1);

    for (int kt = 0; kt < kIters; kt++) {
        if (kt + 1 < kIters) asm volatile("cp.async.wait_group 1;");
        else                 asm volatile("cp.async.wait_group 0;");
        __syncthreads();
        if (kt + 2 < kIters) load_chunk(kt + 2);  // overwrites stage (kt-1)%3

        const __half* At = pool + (kt % 3) * STAGE_H;
        const __half* Bt = At + A_CH;
#pragma unroll
        for (int ks = 0; ks < 2; ks++) {
            const int k0 = ks * 16;

            wmma::fragment<wmma::matrix_a, 16, 16, 16, __half, wmma::row_major> a[4];
            wmma::fragment<wmma::matrix_b, 16, 16, 16, __half, wmma::col_major> b[4];
#pragma unroll
            for (int i = 0; i < 4; i++)
                wmma::load_matrix_sync(a[i], At + (wm * 64 + i * 16) * TSTRIDE + k0, TSTRIDE);
#pragma unroll
            for (int j = 0; j < 4; j++)
                wmma::load_matrix_sync(b[j], Bt + (wn * 64 + j * 16) * TSTRIDE + k0, TSTRIDE);
#pragma unroll
            for (int i = 0; i < 4; i++)
#pragma unroll
                for (int j = 0; j < 4; j++)
                    wmma::mma_sync(acc[i][j], a[i], b[j], acc[i][j]);
        }
    }

    if (OUT_MODE == 0) {
        float* Cf = (float*)Cout;
#pragma unroll
        for (int i = 0; i < 4; i++)
#pragma unroll
            for (int j = 0; j < 4; j++)
                wmma::store_matrix_sync(Cf + (size_t)(wm * 64 + i * 16) * ldc +
                                            wn * 64 + j * 16,
                                        acc[i][j], ldc, wmma::mem_row_major);
    } else if (OUT_MODE == 1) {
        // fp16 output: per j-group stage 64x16 fp32/warp in SMEM, convert.
        __syncthreads();   // pool reuse safe: all warps past final MMA
        __half* Ch = (__half*)Cout;
        float* st = ((float*)pool) + wid * 1024;   // 64x16 fp32 = 4KB/warp
#pragma unroll
        for (int j = 0; j < 4; j++) {
#pragma unroll
            for (int i = 0; i < 4; i++)
                wmma::store_matrix_sync(st + i * 256, acc[i][j], 16, wmma::mem_row_major);
            __syncwarp();
#pragma unroll
            for (int t = 0; t < 16; t++) {
                int idx = lane + t * 32;   // 0..511 half2 units (64x8)
                int row = idx >> 3;        // 0..63
                int c2  = idx & 7;
                __half2 h = __floats2half2_rn(st[row * 16 + c2 * 2],
                                              st[row * 16 + c2 * 2 + 1]);
                *(__half2*)(Ch + (size_t)(wm * 64 + row) * ldc +
                            wn * 64 + j * 16 + c2 * 2) = h;
            }
            __syncwarp();
        }
    } else {
        // Transposed fp16 output (V^T): stage col-major per fragment.
        __syncthreads();   // pool reuse
        __half* Ch = (__half*)Cout;
        float* st = ((float*)pool) + wid * 288;    // 16x17 fp32/warp
#pragma unroll
        for (int i = 0; i < 4; i++) {
#pragma unroll
            for (int j = 0; j < 4; j++) {
                wmma::store_matrix_sync(st, acc[i][j], 17, wmma::mem_col_major);
                __syncwarp();
#pragma unroll
                for (int t = 0; t < 4; t++) {
                    int u  = lane + t * 32;   // 0..127 half2 units
                    int d  = u >> 3;          // 0..15 (dim col of frag)
                    int s2 = u & 7;           // seq pair
                    __half2 h = __floats2half2_rn(st[d * 17 + s2 * 2],
                                                  st[d * 17 + s2 * 2 + 1]);
                    *(__half2*)(Ch + (size_t)(wn * 64 + j * 16 + d) * ldc +
                                wm * 64 + i * 16 + s2 * 2) = h;
                }
                __syncwarp();
            }
        }
    }
}

// ---------------------------------------------------------------------------
// GEMM kernels (all: C = A[M][K] * B[N][K]^T), M-tile 256, N-tile 128
// ---------------------------------------------------------------------------
__global__ void __launch_bounds__(256, 1) qkv_gemm()
{
    const int z = blockIdx.z;
    const __half* W = (z == 0) ? g_wqT : (z == 1) ? g_wkT : g_wvT;
    const __half* A = g_xh + (size_t)blockIdx.y * 256 * DIM;
    const __half* B = W    + (size_t)blockIdx.x * 128 * DIM;

    if (z == 2) {
        // V: write transposed into g_vth[batch][DIM][SEQ]
        const int batch = blockIdx.y >> 3;            // SEQ/256 = 8 blocks/batch
        const int seq0  = (blockIdx.y & 7) * 256;
        __half* C = g_vth + (size_t)batch * DIM * SEQ +
                    (size_t)blockIdx.x * 128 * SEQ + seq0;
        gemm_body<2>(A, B, C, DIM, DIM, SEQ, DIM / BK);
    } else {
        __half* out = (z == 0) ? g_qh : g_kh;
        __half* C = out + (size_t)blockIdx.y * 256 * DIM + (size_t)blockIdx.x * 128;
        gemm_body<1>(A, B, C, DIM, DIM, DIM, DIM / BK);
    }
}

__global__ void __launch_bounds__(256, 1) scores_gemm()
{
    const int bx = blockIdx.x, by = blockIdx.y, b = blockIdx.z;
    if (bx > 2 * by + 1) return;   // tile entirely above causal diagonal
    const __half* A = g_qh + ((size_t)b * SEQ + (size_t)by * 256) * DIM;
    const __half* B = g_kh + ((size_t)b * SEQ + (size_t)bx * 128) * DIM;
    float*        C = g_s  + ((size_t)b * SEQ + (size_t)by * 256) * SEQ + (size_t)bx * 128;
    gemm_body<0>(A, B, C, DIM, DIM, SEQ, DIM / BK);
}

__global__ void __launch_bounds__(256, 1) pv_gemm(float* __restrict__ out)
{
    const int bx = blockIdx.x, by = blockIdx.y, b = blockIdx.z;
    const __half* A = g_p   + ((size_t)b * SEQ + (size_t)by * 256) * SEQ;
    const __half* B = g_vth + (size_t)b * DIM * SEQ + (size_t)bx * 128 * SEQ;
    float*        C = out   + ((size_t)b * SEQ + (size_t)by * 256) * DIM + (size_t)bx * 128;
    gemm_body<0>(A, B, C, SEQ, SEQ, DIM, (by + 1) * (256 / BK));  // K to diag
}

// ---------------------------------------------------------------------------
// Data prep
// ---------------------------------------------------------------------------
__global__ void __launch_bounds__(256) x_to_half(const float* __restrict__ x)
{
    const int N4 = MTOT * DIM / 4;
    for (int i = blockIdx.x * blockDim.x + threadIdx.x; i < N4;
         i += gridDim.x * blockDim.x) {
        float4 v = ((const float4*)x)[i];
        __half2* dst = (__half2*)g_xh + 2 * i;
        dst[0] = __floats2half2_rn(v.x, v.y);
        dst[1] = __floats2half2_rn(v.z, v.w);
    }
}

// W [DIN][DOUT] -> W^T [DOUT][DIN] fp16. grid (32,32,3), block (32,8)
__global__ void wT_half(const float* __restrict__ Wq,
                        const float* __restrict__ Wk,
                        const float* __restrict__ Wv)
{
    __shared__ float t[32][33];
    const float* in   = (blockIdx.z == 0) ? Wq : (blockIdx.z == 1) ? Wk : Wv;
    __half*      out  = (blockIdx.z == 0) ? g_wqT : (blockIdx.z == 1) ? g_wkT : g_wvT;
    const int n0 = blockIdx.x * 32, k0 = blockIdx.y * 32;
    const int tx = threadIdx.x, ty = threadIdx.y;
#pragma unroll
    for (int i = 0; i < 32; i += 8)
        t[ty + i][tx] = in[(size_t)(k0 + ty + i) * DIM + n0 + tx];
    __syncthreads();
#pragma unroll
    for (int i = 0; i < 32; i += 8)
        out[(size_t)(n0 + ty + i) * DIM + k0 + tx] = __float2half_rn(t[tx][ty + i]);
}

// ---------------------------------------------------------------------------
// Causal softmax: fp32 scores in, fp16 probs out. Pads writes to 256-col
// granularity (PV reads K in 256-row M-tiles now).
// ---------------------------------------------------------------------------
__global__ void __launch_bounds__(256) softmax_causal()
{
    __shared__ float red[256];
    const int row = blockIdx.x;
    const int b = row >> 11;
    const int i = row & (SEQ - 1);
    const float* srow = g_s + ((size_t)b * SEQ + i) * SEQ;
    __half*      prow = g_p + ((size_t)b * SEQ + i) * SEQ;
    const int L = i + 1;
    const int Lpad = (L + 255) & ~255;
    const int tid = threadIdx.x;

    float v[8];
    float m = -INFINITY;
#pragma unroll
    for (int u = 0; u < 8; u++) {
        int j = tid + u * 256;
        v[u] = (j < L) ? srow[j] * 0.03125f : -INFINITY;
        m = fmaxf(m, v[u]);
    }
    red[tid] = m;
    __syncthreads();
#pragma unroll
    for (int s = 128; s > 0; s >>= 1) {
        if (tid < s) red[tid] = fmaxf(red[tid], red[tid + s]);
        __syncthreads();
    }
    m = red[0];
    __syncthreads();

    float e[8];
    float sum = 0.0f;
#pragma unroll
    for (int u = 0; u < 8; u++) {
        int j = tid + u * 256;
        e[u] = (j < L) ? __expf(v[u] - m) : 0.0f;
        sum += e[u];
    }
    red[tid] = sum;
    __syncthreads();
#pragma unroll
    for (int s = 128; s > 0; s >>= 1) {
        if (tid < s) red[tid] += red[tid + s];
        __syncthreads();
    }
    const float inv = 1.0f / red[0];

#pragma unroll
    for (int u = 0; u < 8; u++) {
        int j = tid + u * 256;
        if (j < Lpad) prow[j] = __float2half_rn(e[u] * inv);   // j >= L -> 0
    }
}

// ---------------------------------------------------------------------------
extern "C" void kernel_launch(void* const* d_in, const int* in_sizes, int n_in,
                              void* d_out, int out_size)
{
    const float* x  = (const float*)d_in[0];
    const float* Wq = (const float*)d_in[1];
    const float* Wk = (const float*)d_in[2];
    const float* Wv = (const float*)d_in[3];
    float* out = (float*)d_out;

    cudaFuncSetAttribute(qkv_gemm,    cudaFuncAttributeMaxDynamicSharedMemorySize, SMEM_DYN);
    cudaFuncSetAttribute(scores_gemm, cudaFuncAttributeMaxDynamicSharedMemorySize, SMEM_DYN);
    cudaFuncSetAttribute(pv_gemm,     cudaFuncAttributeMaxDynamicSharedMemorySize, SMEM_DYN);

    dim3 gblk(256);
    dim3 tblk(32, 8);

    x_to_half<<<2048, 256>>>(x);
    wT_half<<<dim3(32, 32, 3), tblk>>>(Wq, Wk, Wv);
    qkv_gemm<<<dim3(DIM / 128, MTOT / 256, 3), gblk, SMEM_DYN>>>();
    scores_gemm<<<dim3(SEQ / 128, SEQ / 256, BATCH), gblk, SMEM_DYN>>>();
    softmax_causal<<<dim3(MTOT), 256>>>();
    pv_gemm<<<dim3(DIM / 128, SEQ / 256, BATCH), gblk, SMEM_DYN>>>(out);
}

// round 12
// speedup vs baseline: 1.2159x; 1.2159x over previous
#include <cuda_runtime.h>
#include <cuda_fp16.h>
#include <mma.h>

using namespace nvcuda;

#define BATCH 8
#define SEQ   2048
#define DIM   1024
#define MTOT  (BATCH * SEQ)

// ---------------------------------------------------------------------------
// Device scratch (bss — no runtime allocation)
// ---------------------------------------------------------------------------
__device__ __half g_xh [(size_t)MTOT * DIM];        // x (fp16)
__device__ __half g_qh [(size_t)MTOT * DIM];        // Q (fp16)
__device__ __half g_kh [(size_t)MTOT * DIM];        // K (fp16)
__device__ __half g_vth[(size_t)MTOT * DIM];        // V^T per batch [DIM][SEQ]
__device__ float  g_s  [(size_t)BATCH * SEQ * SEQ]; // scores (fp32)
__device__ __half g_p  [(size_t)BATCH * SEQ * SEQ]; // probs (fp16)
__device__ __half g_wqT[(size_t)DIM * DIM];         // W^T [DOUT][DIN] fp16
__device__ __half g_wkT[(size_t)DIM * DIM];
__device__ __half g_wvT[(size_t)DIM * DIM];

// ---------------------------------------------------------------------------
// cp.async helper (16B)
// ---------------------------------------------------------------------------
__device__ __forceinline__ void cp16(void* dst, const void* src) {
    unsigned sdst = (unsigned)__cvta_generic_to_shared(dst);
    asm volatile("cp.async.cg.shared.global [%0], [%1], 16;" :: "r"(sdst), "l"(src));
}
#define CP_COMMIT() asm volatile("cp.async.commit_group;")

// ---------------------------------------------------------------------------
// fp16 GEMM: C[128,128] = A[128,K] @ B[128,K]^T, fp32 accumulate.
// 256 threads = 8 warps (2m x 4n); warp tile 64x32 = 4x2 m16n16k16 frags.
// BK=64 chunks, 3-stage cp.async pipeline, one barrier per chunk, and
// FRAGMENT DOUBLE-BUFFERING across the 4 K16 steps: LDSM for step ks+1
// issues in the HMMA shadow of step ks (breaks the per-warp LDSM->HMMA
// serialization that pinned tensor at ~50% in R9/R10).
// Dynamic SMEM 110592B; 2 CTAs/SM.
// OUT_MODE: 0 = fp32 direct, 1 = fp16 (staged convert), 2 = fp16 transposed.
// ---------------------------------------------------------------------------
#define BK        64
#define TSTRIDE   72                    // halves per tile row (144B)
#define CHUNK_H   (128 * TSTRIDE)       // halves per matrix chunk (18432B)
#define STAGE_H   (2 * CHUNK_H)         // A+B per stage
#define SMEM_DYN  (3 * STAGE_H * 2)     // 110592B

template <int OUT_MODE>
__device__ __forceinline__ void gemm_body(const __half* __restrict__ A,
                                          const __half* __restrict__ B,
                                          void* __restrict__ Cout,
                                          int lda, int ldb, int ldc, int kIters)
{
    extern __shared__ __align__(16) unsigned char dynraw[];
    __half* pool = (__half*)dynraw;

    const int tid  = threadIdx.x;               // 0..255
    const int wid  = tid >> 5;                  // 0..7
    const int lane = tid & 31;
    const int wm   = wid >> 2;                  // 0..1  (64-row slab)
    const int wn   = wid & 3;                   // 0..3  (32-col slab)

    wmma::fragment<wmma::accumulator, 16, 16, 16, float> acc[4][2];
#pragma unroll
    for (int i = 0; i < 4; i++)
#pragma unroll
        for (int j = 0; j < 2; j++) wmma::fill_fragment(acc[i][j], 0.0f);

    auto load_chunk = [&](int kt) {
        __half* Ad = pool + (kt % 3) * STAGE_H;
        __half* Bd = Ad + CHUNK_H;
#pragma unroll
        for (int u = 0; u < 4; u++) {
            int idx = u * 256 + tid;            // 0..1023
            int row = idx >> 3;                 // 0..127
            int c8  = (idx & 7) * 8;            // half offset 0..56
            cp16(Ad + row * TSTRIDE + c8, A + (size_t)row * lda + kt * BK + c8);
            cp16(Bd + row * TSTRIDE + c8, B + (size_t)row * ldb + kt * BK + c8);
        }
        CP_COMMIT();
    };

    load_chunk(0);
    if (kIters > 1) load_chunk(1);

    // Double-buffered operand fragments
    wmma::fragment<wmma::matrix_a, 16, 16, 16, __half, wmma::row_major> a[2][4];
    wmma::fragment<wmma::matrix_b, 16, 16, 16, __half, wmma::col_major> b[2][2];

    for (int kt = 0; kt < kIters; kt++) {
        if (kt + 1 < kIters) asm volatile("cp.async.wait_group 1;");
        else                 asm volatile("cp.async.wait_group 0;");
        __syncthreads();
        if (kt + 2 < kIters) load_chunk(kt + 2);   // writes stage (kt-1)%3: free

        const __half* At = pool + (kt % 3) * STAGE_H;
        const __half* Bt = At + CHUNK_H;

        // Preload step 0 fragments
#pragma unroll
        for (int i = 0; i < 4; i++)
            wmma::load_matrix_sync(a[0][i], At + (wm * 64 + i * 16) * TSTRIDE, TSTRIDE);
#pragma unroll
        for (int j = 0; j < 2; j++)
            wmma::load_matrix_sync(b[0][j], Bt + (wn * 32 + j * 16) * TSTRIDE, TSTRIDE);

#pragma unroll
        for (int ks = 0; ks < 4; ks++) {
            const int cu = ks & 1;
            if (ks + 1 < 4) {
                const int k1 = (ks + 1) * 16;
#pragma unroll
                for (int i = 0; i < 4; i++)
                    wmma::load_matrix_sync(a[cu ^ 1][i],
                        At + (wm * 64 + i * 16) * TSTRIDE + k1, TSTRIDE);
#pragma unroll
                for (int j = 0; j < 2; j++)
                    wmma::load_matrix_sync(b[cu ^ 1][j],
                        Bt + (wn * 32 + j * 16) * TSTRIDE + k1, TSTRIDE);
            }
#pragma unroll
            for (int i = 0; i < 4; i++)
#pragma unroll
                for (int j = 0; j < 2; j++)
                    wmma::mma_sync(acc[i][j], a[cu][i], b[cu][j], acc[i][j]);
        }
    }

    if (OUT_MODE == 0) {
        float* Cf = (float*)Cout;
#pragma unroll
        for (int i = 0; i < 4; i++)
#pragma unroll
            for (int j = 0; j < 2; j++)
                wmma::store_matrix_sync(Cf + (size_t)(wm * 64 + i * 16) * ldc +
                                            wn * 32 + j * 16,
                                        acc[i][j], ldc, wmma::mem_row_major);
    } else if (OUT_MODE == 1) {
        // fp16 output: stage 64x32 fp32 per warp in SMEM, convert, write half2.
        __syncthreads();   // pool reuse: all warps done with final stage
        __half* Ch = (__half*)Cout;
        float* st = ((float*)pool) + wid * 2048;    // 64x32 fp32 = 8KB/warp
#pragma unroll
        for (int i = 0; i < 4; i++)
#pragma unroll
            for (int j = 0; j < 2; j++)
                wmma::store_matrix_sync(st + (i * 16) * 32 + j * 16, acc[i][j],
                                        32, wmma::mem_row_major);
        __syncwarp();
#pragma unroll
        for (int t = 0; t < 32; t++) {
            int idx = lane + t * 32;    // 0..1023 half2 units
            int row = idx >> 4;         // 0..63
            int c2  = idx & 15;         // half2 col
            __half2 h = __floats2half2_rn(st[row * 32 + c2 * 2],
                                          st[row * 32 + c2 * 2 + 1]);
            *(__half2*)(Ch + (size_t)(wm * 64 + row) * ldc +
                        wn * 32 + c2 * 2) = h;
        }
    } else {
        // Transposed fp16 output (V^T): stage col-major per fragment.
        __syncthreads();   // pool reuse
        __half* Ch = (__half*)Cout;
        float* st = ((float*)pool) + wid * 288;     // 16x17 fp32 per warp
#pragma unroll
        for (int i = 0; i < 4; i++) {
#pragma unroll
            for (int j = 0; j < 2; j++) {
                wmma::store_matrix_sync(st, acc[i][j], 17, wmma::mem_col_major);
                __syncwarp();
#pragma unroll
                for (int t = 0; t < 4; t++) {
                    int u  = lane + t * 32;   // 0..127 half2 units
                    int d  = u >> 3;          // 0..15 (dim)
                    int s2 = u & 7;           // seq pair
                    __half2 h = __floats2half2_rn(st[d * 17 + s2 * 2],
                                                  st[d * 17 + s2 * 2 + 1]);
                    *(__half2*)(Ch + (size_t)(wn * 32 + j * 16 + d) * ldc +
                                wm * 64 + i * 16 + s2 * 2) = h;
                }
                __syncwarp();
            }
        }
    }
}

// ---------------------------------------------------------------------------
// GEMM kernels (all: C = A[M][K] * B[N][K]^T)
// ---------------------------------------------------------------------------
__global__ void __launch_bounds__(256, 2) qkv_gemm()
{
    const int z = blockIdx.z;
    const __half* W = (z == 0) ? g_wqT : (z == 1) ? g_wkT : g_wvT;
    const __half* A = g_xh + (size_t)blockIdx.y * 128 * DIM;
    const __half* B = W    + (size_t)blockIdx.x * 128 * DIM;

    if (z == 2) {
        // V: write transposed into g_vth[batch][DIM][SEQ]
        const int batch = blockIdx.y >> 4;            // SEQ/128 = 16 blocks/batch
        const int seq0  = (blockIdx.y & 15) * 128;
        __half* C = g_vth + (size_t)batch * DIM * SEQ +
                    (size_t)blockIdx.x * 128 * SEQ + seq0;
        gemm_body<2>(A, B, C, DIM, DIM, SEQ, DIM / BK);
    } else {
        __half* out = (z == 0) ? g_qh : g_kh;
        __half* C = out + (size_t)blockIdx.y * 128 * DIM + (size_t)blockIdx.x * 128;
        gemm_body<1>(A, B, C, DIM, DIM, DIM, DIM / BK);
    }
}

__global__ void __launch_bounds__(256, 2) scores_gemm()
{
    const int bx = blockIdx.x, by = blockIdx.y, b = blockIdx.z;
    if (bx > by) return;   // strictly above causal diagonal: never read
    const __half* A = g_qh + ((size_t)b * SEQ + (size_t)by * 128) * DIM;
    const __half* B = g_kh + ((size_t)b * SEQ + (size_t)bx * 128) * DIM;
    float*        C = g_s  + ((size_t)b * SEQ + (size_t)by * 128) * SEQ + (size_t)bx * 128;
    gemm_body<0>(A, B, C, DIM, DIM, SEQ, DIM / BK);
}

__global__ void __launch_bounds__(256, 2) pv_gemm(float* __restrict__ out)
{
    const int bx = blockIdx.x, by = blockIdx.y, b = blockIdx.z;
    const __half* A = g_p   + ((size_t)b * SEQ + (size_t)by * 128) * SEQ;
    const __half* B = g_vth + (size_t)b * DIM * SEQ + (size_t)bx * 128 * SEQ;
    float*        C = out   + ((size_t)b * SEQ + (size_t)by * 128) * DIM + (size_t)bx * 128;
    gemm_body<0>(A, B, C, SEQ, SEQ, DIM, (by + 1) * (128 / BK));  // K to diag
}

// ---------------------------------------------------------------------------
// Data prep
// ---------------------------------------------------------------------------
__global__ void __launch_bounds__(256) x_to_half(const float* __restrict__ x)
{
    const int N4 = MTOT * DIM / 4;
    for (int i = blockIdx.x * blockDim.x + threadIdx.x; i < N4;
         i += gridDim.x * blockDim.x) {
        float4 v = ((const float4*)x)[i];
        __half2* dst = (__half2*)g_xh + 2 * i;
        dst[0] = __floats2half2_rn(v.x, v.y);
        dst[1] = __floats2half2_rn(v.z, v.w);
    }
}

// W [DIN][DOUT] -> W^T [DOUT][DIN] fp16. grid (32,32,3), block (32,8)
__global__ void wT_half(const float* __restrict__ Wq,
                        const float* __restrict__ Wk,
                        const float* __restrict__ Wv)
{
    __shared__ float t[32][33];
    const float* in   = (blockIdx.z == 0) ? Wq : (blockIdx.z == 1) ? Wk : Wv;
    __half*      out  = (blockIdx.z == 0) ? g_wqT : (blockIdx.z == 1) ? g_wkT : g_wvT;
    const int n0 = blockIdx.x * 32, k0 = blockIdx.y * 32;
    const int tx = threadIdx.x, ty = threadIdx.y;
#pragma unroll
    for (int i = 0; i < 32; i += 8)
        t[ty + i][tx] = in[(size_t)(k0 + ty + i) * DIM + n0 + tx];
    __syncthreads();
#pragma unroll
    for (int i = 0; i < 32; i += 8)
        out[(size_t)(n0 + ty + i) * DIM + k0 + tx] = __float2half_rn(t[tx][ty + i]);
}

// ---------------------------------------------------------------------------
// Causal softmax: fp32 scores in, fp16 probs out. Writes only the columns PV
// reads: [0, ceil(L/128)*128).
// ---------------------------------------------------------------------------
__global__ void __launch_bounds__(256) softmax_causal()
{
    __shared__ float red[256];
    const int row = blockIdx.x;
    const int b = row >> 11;
    const int i = row & (SEQ - 1);
    const float* srow = g_s + ((size_t)b * SEQ + i) * SEQ;
    __half*      prow = g_p + ((size_t)b * SEQ + i) * SEQ;
    const int L = i + 1;
    const int Lpad = (L + 127) & ~127;
    const int tid = threadIdx.x;

    float v[8];
    float m = -INFINITY;
#pragma unroll
    for (int u = 0; u < 8; u++) {
        int j = tid + u * 256;
        v[u] = (j < L) ? srow[j] * 0.03125f : -INFINITY;
        m = fmaxf(m, v[u]);
    }
    red[tid] = m;
    __syncthreads();
#pragma unroll
    for (int s = 128; s > 0; s >>= 1) {
        if (tid < s) red[tid] = fmaxf(red[tid], red[tid + s]);
        __syncthreads();
    }
    m = red[0];
    __syncthreads();

    float e[8];
    float sum = 0.0f;
#pragma unroll
    for (int u = 0; u < 8; u++) {
        int j = tid + u * 256;
        e[u] = (j < L) ? __expf(v[u] - m) : 0.0f;
        sum += e[u];
    }
    red[tid] = sum;
    __syncthreads();
#pragma unroll
    for (int s = 128; s > 0; s >>= 1) {
        if (tid < s) red[tid] += red[tid + s];
        __syncthreads();
    }
    const float inv = 1.0f / red[0];

#pragma unroll
    for (int u = 0; u < 8; u++) {
        int j = tid + u * 256;
        if (j < Lpad) prow[j] = __float2half_rn(e[u] * inv);   // j >= L -> 0
    }
}

// ---------------------------------------------------------------------------
extern "C" void kernel_launch(void* const* d_in, const int* in_sizes, int n_in,
                              void* d_out, int out_size)
{
    const float* x  = (const float*)d_in[0];
    const float* Wq = (const float*)d_in[1];
    const float* Wk = (const float*)d_in[2];
    const float* Wv = (const float*)d_in[3];
    float* out = (float*)d_out;

    cudaFuncSetAttribute(qkv_gemm,    cudaFuncAttributeMaxDynamicSharedMemorySize, SMEM_DYN);
    cudaFuncSetAttribute(scores_gemm, cudaFuncAttributeMaxDynamicSharedMemorySize, SMEM_DYN);
    cudaFuncSetAttribute(pv_gemm,     cudaFuncAttributeMaxDynamicSharedMemorySize, SMEM_DYN);

    dim3 gblk(256);
    dim3 tblk(32, 8);

    x_to_half<<<2048, 256>>>(x);
    wT_half<<<dim3(32, 32, 3), tblk>>>(Wq, Wk, Wv);
    qkv_gemm<<<dim3(DIM / 128, MTOT / 128, 3), gblk, SMEM_DYN>>>();
    scores_gemm<<<dim3(SEQ / 128, SEQ / 128, BATCH), gblk, SMEM_DYN>>>();
    softmax_causal<<<dim3(MTOT), 256>>>();
    pv_gemm<<<dim3(DIM / 128, SEQ / 128, BATCH), gblk, SMEM_DYN>>>(out);
}

// round 13
// speedup vs baseline: 1.3173x; 1.0834x over previous
#include <cuda_runtime.h>
#include <cuda_fp16.h>

#define BATCH 8
#define SEQ   2048
#define DIM   1024
#define MTOT  (BATCH * SEQ)

// ---------------------------------------------------------------------------
// Device scratch (bss — no runtime allocation)
// ---------------------------------------------------------------------------
__device__ __half g_xh [(size_t)MTOT * DIM];        // x (fp16)
__device__ __half g_qh [(size_t)MTOT * DIM];        // Q (fp16)
__device__ __half g_kh [(size_t)MTOT * DIM];        // K (fp16)
__device__ __half g_vh [(size_t)MTOT * DIM];        // V (fp16, natural layout)
__device__ float  g_s  [(size_t)BATCH * SEQ * SEQ]; // scores (fp32)
__device__ __half g_p  [(size_t)BATCH * SEQ * SEQ]; // probs (fp16)
__device__ __half g_wqT[(size_t)DIM * DIM];         // W^T [DOUT][DIN] fp16
__device__ __half g_wkT[(size_t)DIM * DIM];
__device__ __half g_wvT[(size_t)DIM * DIM];

// ---------------------------------------------------------------------------
// PTX helpers
// ---------------------------------------------------------------------------
__device__ __forceinline__ void cp16(void* dst, const void* src) {
    unsigned sdst = (unsigned)__cvta_generic_to_shared(dst);
    asm volatile("cp.async.cg.shared.global [%0], [%1], 16;" :: "r"(sdst), "l"(src));
}
#define CP_COMMIT() asm volatile("cp.async.commit_group;")

#define LDSM_X4(r, addr)                                                        \
    asm volatile("ldmatrix.sync.aligned.m8n8.x4.shared.b16 {%0,%1,%2,%3}, [%4];"\
                 : "=r"((r)[0]), "=r"((r)[1]), "=r"((r)[2]), "=r"((r)[3])       \
                 : "r"(addr))

#define LDSM_X4T(r, addr)                                                       \
    asm volatile("ldmatrix.sync.aligned.m8n8.x4.trans.shared.b16 {%0,%1,%2,%3}, [%4];" \
                 : "=r"((r)[0]), "=r"((r)[1]), "=r"((r)[2]), "=r"((r)[3])       \
                 : "r"(addr))

#define MMA_OP(d, a, b)                                                         \
    asm volatile("mma.sync.aligned.m16n8k16.row.col.f32.f16.f16.f32 "           \
                 "{%0,%1,%2,%3}, {%4,%5,%6,%7}, {%8,%9}, {%0,%1,%2,%3};"        \
                 : "+f"((d)[0]), "+f"((d)[1]), "+f"((d)[2]), "+f"((d)[3])       \
                 : "r"((a)[0]), "r"((a)[1]), "r"((a)[2]), "r"((a)[3]),          \
                   "r"((b)[0]), "r"((b)[1]))

// ---------------------------------------------------------------------------
// fp16 GEMM: C[128,128] = A[128,K] @ Bop, fp32 accumulate.
// 256 threads = 8 warps (2m x 4n); warp tile 64x32 = 4x4 m16n8k16 mma tiles.
// TRANSB=false: B memory [n=128][k] K-major (scores/QKV), ldmatrix non-trans.
// TRANSB=true : B memory [k][n] natural (PV on V), ldmatrix.x4.trans.
// Raw ldmatrix/mma with register double-buffering across the 4 K16 steps,
// next-step LDSM interleaved among current-step MMAs in asm-volatile order
// (wmma collapsed this in R12; raw asm can't be collapsed).
// BK=64, 3-stage cp.async pipeline, one barrier per chunk. SMEM 110592B.
// OUT_MODE: 0 = fp32 direct, 1 = fp16 direct.
// ---------------------------------------------------------------------------
#define BK          64
#define A_STRIDE_H  72          // 144B rows (A and non-trans B): 36w = +4 banks/row
#define BT_STRIDE_H 136         // 272B rows (trans B): 68w = +4 banks/row
#define A_H         (128 * A_STRIDE_H)     // 9216 halves
#define STAGE_HV    18432                  // halves per stage (A + B slot)
#define STAGE_B     (STAGE_HV * 2)         // 36864 bytes
#define SMEM_DYN    (3 * STAGE_B)          // 110592 bytes

template <bool TRANSB, int OUT_MODE>
__device__ __forceinline__ void gemm_body(const __half* __restrict__ A,
                                          const __half* __restrict__ B,
                                          void* __restrict__ Cout,
                                          int lda, int ldb, int ldc, int kIters)
{
    extern __shared__ __align__(16) unsigned char dynraw[];
    __half* pool = (__half*)dynraw;
    const unsigned sbase = (unsigned)__cvta_generic_to_shared(dynraw);

    const int tid = threadIdx.x;
    const int wid = tid >> 5;
    const int l   = tid & 31;
    const int wm  = wid >> 2;            // 0..1
    const int wn  = wid & 3;             // 0..3

    float acc[4][4][4];
#pragma unroll
    for (int i = 0; i < 4; i++)
#pragma unroll
        for (int j = 0; j < 4; j++)
#pragma unroll
            for (int t = 0; t < 4; t++) acc[i][j][t] = 0.0f;

    // ldmatrix per-lane byte offsets (within stage)
    // A frag (m16k16): lanes 0-15 rows m0-15 @k0, lanes 16-31 same rows @k8
    unsigned aoff[4];
#pragma unroll
    for (int i = 0; i < 4; i++)
        aoff[i] = (unsigned)((wm * 64 + i * 16 + (l & 15)) * 144 + (l >> 4) * 16);
    // B non-trans x4 (n16k16): lanes0-7 n0-7@k0, 8-15 n0-7@k8, 16-23 n8-15@k0, 24-31 n8-15@k8
    unsigned boff[2];
#pragma unroll
    for (int jj = 0; jj < 2; jj++)
        boff[jj] = (unsigned)(A_H * 2 +
                   (wn * 32 + jj * 16 + (l & 7) + ((l >> 4) & 1) * 8) * 144 +
                   ((l >> 3) & 1) * 16);
    // B trans x4 from [k][n]: lanes0-7 k0-7@n0, 8-15 k8-15@n0, 16-23 k0-7@n8, 24-31 k8-15@n8
    unsigned btoff[2];
#pragma unroll
    for (int jj = 0; jj < 2; jj++)
        btoff[jj] = (unsigned)(A_H * 2 +
                    ((l & 7) + ((l >> 3) & 1) * 8) * 272 +
                    ((l >> 4) & 1) * 16 + (wn * 32 + jj * 16) * 2);

    auto load_chunk = [&](int kt) {
        __half* Ad = pool + (kt % 3) * STAGE_HV;
        __half* Bd = Ad + A_H;
#pragma unroll
        for (int u = 0; u < 4; u++) {                // A: 128 x 64 halves
            int idx = u * 256 + tid;
            int row = idx >> 3;
            int c8  = (idx & 7) * 8;
            cp16(Ad + row * A_STRIDE_H + c8, A + (size_t)row * lda + kt * BK + c8);
        }
        if (TRANSB) {
#pragma unroll
            for (int u = 0; u < 4; u++) {            // B: 64 k-rows x 128 n halves
                int idx = u * 256 + tid;
                int row = idx >> 4;                  // 0..63
                int c   = (idx & 15) * 8;            // 0..120
                cp16(Bd + row * BT_STRIDE_H + c, B + (size_t)(kt * BK + row) * ldb + c);
            }
        } else {
#pragma unroll
            for (int u = 0; u < 4; u++) {            // B: 128 n-rows x 64 halves
                int idx = u * 256 + tid;
                int row = idx >> 3;
                int c8  = (idx & 7) * 8;
                cp16(Bd + row * A_STRIDE_H + c8, B + (size_t)row * ldb + kt * BK + c8);
            }
        }
        CP_COMMIT();
    };

    load_chunk(0);
    if (kIters > 1) load_chunk(1);

    unsigned a[2][4][4];        // [buf][i][regs]
    unsigned b[2][4][2];        // [buf][j][regs]  (x4 fills j, j+1 pairs)

    const unsigned bstep = TRANSB ? (16u * 272u) : 32u;  // per-K16 byte advance

    for (int kt = 0; kt < kIters; kt++) {
        if (kt + 1 < kIters) asm volatile("cp.async.wait_group 1;");
        else                 asm volatile("cp.async.wait_group 0;");
        __syncthreads();
        if (kt + 2 < kIters) load_chunk(kt + 2);   // stage (kt-1)%3: consumed

        const unsigned stg = sbase + (unsigned)(kt % 3) * STAGE_B;

        // preload ks=0 fragments into buf 0
#pragma unroll
        for (int i = 0; i < 4; i++) LDSM_X4(a[0][i], stg + aoff[i]);
        if (TRANSB) { LDSM_X4T(&b[0][0][0], stg + btoff[0]); LDSM_X4T(&b[0][2][0], stg + btoff[1]); }
        else        { LDSM_X4 (&b[0][0][0], stg + boff[0]);  LDSM_X4 (&b[0][2][0], stg + boff[1]);  }

#pragma unroll
        for (int ks = 0; ks < 4; ks++) {
            const int cu = ks & 1, nb = cu ^ 1;
            if (ks < 3) {
                const unsigned ka = stg + (unsigned)(ks + 1) * 32u;
                const unsigned kb = stg + (unsigned)(ks + 1) * bstep;
                // interleave next-step LDSM among current-step MMAs
                LDSM_X4(a[nb][0], ka + aoff[0]);
#pragma unroll
                for (int i = 0; i < 4; i++) MMA_OP(acc[i][0], a[cu][i], b[cu][0]);
                LDSM_X4(a[nb][1], ka + aoff[1]);
#pragma unroll
                for (int i = 0; i < 4; i++) MMA_OP(acc[i][1], a[cu][i], b[cu][1]);
                LDSM_X4(a[nb][2], ka + aoff[2]);
#pragma unroll
                for (int i = 0; i < 4; i++) MMA_OP(acc[i][2], a[cu][i], b[cu][2]);
                LDSM_X4(a[nb][3], ka + aoff[3]);
                MMA_OP(acc[0][3], a[cu][0], b[cu][3]);
                MMA_OP(acc[1][3], a[cu][1], b[cu][3]);
                if (TRANSB) LDSM_X4T(&b[nb][0][0], kb + btoff[0]);
                else        LDSM_X4 (&b[nb][0][0], kb + boff[0]);
                MMA_OP(acc[2][3], a[cu][2], b[cu][3]);
                if (TRANSB) LDSM_X4T(&b[nb][2][0], kb + btoff[1]);
                else        LDSM_X4 (&b[nb][2][0], kb + boff[1]);
                MMA_OP(acc[3][3], a[cu][3], b[cu][3]);
            } else {
#pragma unroll
                for (int j = 0; j < 4; j++)
#pragma unroll
                    for (int i = 0; i < 4; i++)
                        MMA_OP(acc[i][j], a[cu][i], b[cu][j]);
            }
        }
    }

    // Epilogue: direct fragment stores (acc tile m16n8; lane l: rows l/4, l/4+8,
    // cols 2*(l%4), +1)
    const int r0 = l >> 2;
    const int c0 = wn * 32 + 2 * (l & 3);
    if (OUT_MODE == 0) {
        float* Cf = (float*)Cout;
#pragma unroll
        for (int i = 0; i < 4; i++)
#pragma unroll
            for (int j = 0; j < 4; j++) {
                int row = wm * 64 + i * 16 + r0;
                int col = c0 + j * 8;
                *(float2*)(Cf + (size_t)row * ldc + col) =
                    make_float2(acc[i][j][0], acc[i][j][1]);
                *(float2*)(Cf + (size_t)(row + 8) * ldc + col) =
                    make_float2(acc[i][j][2], acc[i][j][3]);
            }
    } else {
        __half* Ch = (__half*)Cout;
#pragma unroll
        for (int i = 0; i < 4; i++)
#pragma unroll
            for (int j = 0; j < 4; j++) {
                int row = wm * 64 + i * 16 + r0;
                int col = c0 + j * 8;
                *(__half2*)(Ch + (size_t)row * ldc + col) =
                    __floats2half2_rn(acc[i][j][0], acc[i][j][1]);
                *(__half2*)(Ch + (size_t)(row + 8) * ldc + col) =
                    __floats2half2_rn(acc[i][j][2], acc[i][j][3]);
            }
    }
}

// ---------------------------------------------------------------------------
// GEMM kernels
// ---------------------------------------------------------------------------
__global__ void __launch_bounds__(256, 2) qkv_gemm()
{
    const int z = blockIdx.z;
    const __half* W   = (z == 0) ? g_wqT : (z == 1) ? g_wkT : g_wvT;
    __half*       out = (z == 0) ? g_qh  : (z == 1) ? g_kh  : g_vh;
    const __half* A = g_xh + (size_t)blockIdx.y * 128 * DIM;
    const __half* B = W    + (size_t)blockIdx.x * 128 * DIM;
    __half*       C = out  + (size_t)blockIdx.y * 128 * DIM + (size_t)blockIdx.x * 128;
    gemm_body<false, 1>(A, B, C, DIM, DIM, DIM, DIM / BK);
}

__global__ void __launch_bounds__(256, 2) scores_gemm()
{
    const int bx = blockIdx.x, by = blockIdx.y, b = blockIdx.z;
    if (bx > by) return;   // strictly above causal diagonal: never read
    const __half* A = g_qh + ((size_t)b * SEQ + (size_t)by * 128) * DIM;
    const __half* B = g_kh + ((size_t)b * SEQ + (size_t)bx * 128) * DIM;
    float*        C = g_s  + ((size_t)b * SEQ + (size_t)by * 128) * SEQ + (size_t)bx * 128;
    gemm_body<false, 0>(A, B, C, DIM, DIM, SEQ, DIM / BK);
}

__global__ void __launch_bounds__(256, 2) pv_gemm(float* __restrict__ out)
{
    const int bx = blockIdx.x, by = blockIdx.y, b = blockIdx.z;
    const __half* A = g_p  + ((size_t)b * SEQ + (size_t)by * 128) * SEQ;
    const __half* B = g_vh + (size_t)b * SEQ * DIM + (size_t)bx * 128;  // natural V
    float*        C = out  + ((size_t)b * SEQ + (size_t)by * 128) * DIM + (size_t)bx * 128;
    gemm_body<true, 0>(A, B, C, SEQ, DIM, DIM, (by + 1) * 2);  // K to diag, BK=64
}

// ---------------------------------------------------------------------------
// Data prep
// ---------------------------------------------------------------------------
__global__ void __launch_bounds__(256) x_to_half(const float* __restrict__ x)
{
    const int N4 = MTOT * DIM / 4;
    for (int i = blockIdx.x * blockDim.x + threadIdx.x; i < N4;
         i += gridDim.x * blockDim.x) {
        float4 v = ((const float4*)x)[i];
        __half2* dst = (__half2*)g_xh + 2 * i;
        dst[0] = __floats2half2_rn(v.x, v.y);
        dst[1] = __floats2half2_rn(v.z, v.w);
    }
}

// W [DIN][DOUT] -> W^T [DOUT][DIN] fp16. grid (32,32,3), block (32,8)
__global__ void wT_half(const float* __restrict__ Wq,
                        const float* __restrict__ Wk,
                        const float* __restrict__ Wv)
{
    __shared__ float t[32][33];
    const float* in   = (blockIdx.z == 0) ? Wq : (blockIdx.z == 1) ? Wk : Wv;
    __half*      out  = (blockIdx.z == 0) ? g_wqT : (blockIdx.z == 1) ? g_wkT : g_wvT;
    const int n0 = blockIdx.x * 32, k0 = blockIdx.y * 32;
    const int tx = threadIdx.x, ty = threadIdx.y;
#pragma unroll
    for (int i = 0; i < 32; i += 8)
        t[ty + i][tx] = in[(size_t)(k0 + ty + i) * DIM + n0 + tx];
    __syncthreads();
#pragma unroll
    for (int i = 0; i < 32; i += 8)
        out[(size_t)(n0 + ty + i) * DIM + k0 + tx] = __float2half_rn(t[tx][ty + i]);
}

// ---------------------------------------------------------------------------
// Causal softmax: fp32 scores in, fp16 probs out. Writes only the columns PV
// reads: [0, ceil(L/128)*128).
// ---------------------------------------------------------------------------
__global__ void __launch_bounds__(256) softmax_causal()
{
    __shared__ float red[256];
    const int row = blockIdx.x;
    const int b = row >> 11;
    const int i = row & (SEQ - 1);
    const float* srow = g_s + ((size_t)b * SEQ + i) * SEQ;
    __half*      prow = g_p + ((size_t)b * SEQ + i) * SEQ;
    const int L = i + 1;
    const int Lpad = (L + 127) & ~127;
    const int tid = threadIdx.x;

    float v[8];
    float m = -INFINITY;
#pragma unroll
    for (int u = 0; u < 8; u++) {
        int j = tid + u * 256;
        v[u] = (j < L) ? srow[j] * 0.03125f : -INFINITY;
        m = fmaxf(m, v[u]);
    }
    red[tid] = m;
    __syncthreads();
#pragma unroll
    for (int s = 128; s > 0; s >>= 1) {
        if (tid < s) red[tid] = fmaxf(red[tid], red[tid + s]);
        __syncthreads();
    }
    m = red[0];
    __syncthreads();

    float e[8];
    float sum = 0.0f;
#pragma unroll
    for (int u = 0; u < 8; u++) {
        int j = tid + u * 256;
        e[u] = (j < L) ? __expf(v[u] - m) : 0.0f;
        sum += e[u];
    }
    red[tid] = sum;
    __syncthreads();
#pragma unroll
    for (int s = 128; s > 0; s >>= 1) {
        if (tid < s) red[tid] += red[tid + s];
        __syncthreads();
    }
    const float inv = 1.0f / red[0];

#pragma unroll
    for (int u = 0; u < 8; u++) {
        int j = tid + u * 256;
        if (j < Lpad) prow[j] = __float2half_rn(e[u] * inv);   // j >= L -> 0
    }
}

// ---------------------------------------------------------------------------
extern "C" void kernel_launch(void* const* d_in, const int* in_sizes, int n_in,
                              void* d_out, int out_size)
{
    const float* x  = (const float*)d_in[0];
    const float* Wq = (const float*)d_in[1];
    const float* Wk = (const float*)d_in[2];
    const float* Wv = (const float*)d_in[3];
    float* out = (float*)d_out;

    cudaFuncSetAttribute(qkv_gemm,    cudaFuncAttributeMaxDynamicSharedMemorySize, SMEM_DYN);
    cudaFuncSetAttribute(scores_gemm, cudaFuncAttributeMaxDynamicSharedMemorySize, SMEM_DYN);
    cudaFuncSetAttribute(pv_gemm,     cudaFuncAttributeMaxDynamicSharedMemorySize, SMEM_DYN);

    dim3 gblk(256);
    dim3 tblk(32, 8);

    x_to_half<<<2048, 256>>>(x);
    wT_half<<<dim3(32, 32, 3), tblk>>>(Wq, Wk, Wv);
    qkv_gemm<<<dim3(DIM / 128, MTOT / 128, 3), gblk, SMEM_DYN>>>();
    scores_gemm<<<dim3(SEQ / 128, SEQ / 128, BATCH), gblk, SMEM_DYN>>>();
    softmax_causal<<<dim3(MTOT), 256>>>();
    pv_gemm<<<dim3(DIM / 128, SEQ / 128, BATCH), gblk, SMEM_DYN>>>(out);
}

// round 14
// speedup vs baseline: 1.3473x; 1.0228x over previous
#include <cuda_runtime.h>
#include <cuda_fp16.h>

#define BATCH 8
#define SEQ   2048
#define DIM   1024
#define MTOT  (BATCH * SEQ)

// ---------------------------------------------------------------------------
// Device scratch (bss — no runtime allocation)
// ---------------------------------------------------------------------------
__device__ __half g_xh [(size_t)MTOT * DIM];        // x (fp16)
__device__ __half g_qh [(size_t)MTOT * DIM];        // Q (fp16)
__device__ __half g_kh [(size_t)MTOT * DIM];        // K (fp16)
__device__ __half g_vh [(size_t)MTOT * DIM];        // V (fp16, natural layout)
__device__ float  g_s  [(size_t)BATCH * SEQ * SEQ]; // scores (fp32)
__device__ __half g_p  [(size_t)BATCH * SEQ * SEQ]; // probs (fp16)
__device__ __half g_wqT[(size_t)DIM * DIM];         // W^T [DOUT][DIN] fp16
__device__ __half g_wkT[(size_t)DIM * DIM];
__device__ __half g_wvT[(size_t)DIM * DIM];

// ---------------------------------------------------------------------------
// PTX helpers
// ---------------------------------------------------------------------------
__device__ __forceinline__ void cp16(void* dst, const void* src) {
    unsigned sdst = (unsigned)__cvta_generic_to_shared(dst);
    asm volatile("cp.async.cg.shared.global [%0], [%1], 16;" :: "r"(sdst), "l"(src));
}
#define CP_COMMIT() asm volatile("cp.async.commit_group;")

#define LDSM_X4(r, addr)                                                        \
    asm volatile("ldmatrix.sync.aligned.m8n8.x4.shared.b16 {%0,%1,%2,%3}, [%4];"\
                 : "=r"((r)[0]), "=r"((r)[1]), "=r"((r)[2]), "=r"((r)[3])       \
                 : "r"(addr))

#define LDSM_X4T(r, addr)                                                       \
    asm volatile("ldmatrix.sync.aligned.m8n8.x4.trans.shared.b16 {%0,%1,%2,%3}, [%4];" \
                 : "=r"((r)[0]), "=r"((r)[1]), "=r"((r)[2]), "=r"((r)[3])       \
                 : "r"(addr))

#define MMA_OP(d, a, b)                                                         \
    asm volatile("mma.sync.aligned.m16n8k16.row.col.f32.f16.f16.f32 "           \
                 "{%0,%1,%2,%3}, {%4,%5,%6,%7}, {%8,%9}, {%0,%1,%2,%3};"        \
                 : "+f"((d)[0]), "+f"((d)[1]), "+f"((d)[2]), "+f"((d)[3])       \
                 : "r"((a)[0]), "r"((a)[1]), "r"((a)[2]), "r"((a)[3]),          \
                   "r"((b)[0]), "r"((b)[1]))

// ---------------------------------------------------------------------------
// fp16 GEMM: C[128,128] = A[128,K] @ Bop, fp32 accumulate.
// 256 threads = 8 warps (2m x 4n); warp tile 64x32 = 4x4 m16n8k16 mma tiles.
// Raw ldmatrix/mma, register double-buffered K16 steps, LDSM interleaved
// among MMAs. Measured: smem crossbar ~88% busy — this body is at its
// bandwidth-bound limit for the register budget. (see R13 post-mortem)
// ---------------------------------------------------------------------------
#define BK          64
#define A_STRIDE_H  72          // 144B rows: +4 banks/row -> conflict-free LDSM
#define BT_STRIDE_H 136         // 272B rows (trans B): +4 banks/row
#define A_H         (128 * A_STRIDE_H)     // 9216 halves
#define STAGE_HV    18432                  // halves per stage (A + B slot)
#define STAGE_B     (STAGE_HV * 2)         // 36864 bytes
#define SMEM_DYN    (3 * STAGE_B)          // 110592 bytes

template <bool TRANSB, int OUT_MODE>
__device__ __forceinline__ void gemm_body(const __half* __restrict__ A,
                                          const __half* __restrict__ B,
                                          void* __restrict__ Cout,
                                          int lda, int ldb, int ldc, int kIters)
{
    extern __shared__ __align__(16) unsigned char dynraw[];
    __half* pool = (__half*)dynraw;
    const unsigned sbase = (unsigned)__cvta_generic_to_shared(dynraw);

    const int tid = threadIdx.x;
    const int wid = tid >> 5;
    const int l   = tid & 31;
    const int wm  = wid >> 2;            // 0..1
    const int wn  = wid & 3;             // 0..3

    float acc[4][4][4];
#pragma unroll
    for (int i = 0; i < 4; i++)
#pragma unroll
        for (int j = 0; j < 4; j++)
#pragma unroll
            for (int t = 0; t < 4; t++) acc[i][j][t] = 0.0f;

    unsigned aoff[4];
#pragma unroll
    for (int i = 0; i < 4; i++)
        aoff[i] = (unsigned)((wm * 64 + i * 16 + (l & 15)) * 144 + (l >> 4) * 16);
    unsigned boff[2];
#pragma unroll
    for (int jj = 0; jj < 2; jj++)
        boff[jj] = (unsigned)(A_H * 2 +
                   (wn * 32 + jj * 16 + (l & 7) + ((l >> 4) & 1) * 8) * 144 +
                   ((l >> 3) & 1) * 16);
    unsigned btoff[2];
#pragma unroll
    for (int jj = 0; jj < 2; jj++)
        btoff[jj] = (unsigned)(A_H * 2 +
                    ((l & 7) + ((l >> 3) & 1) * 8) * 272 +
                    ((l >> 4) & 1) * 16 + (wn * 32 + jj * 16) * 2);

    auto load_chunk = [&](int kt) {
        __half* Ad = pool + (kt % 3) * STAGE_HV;
        __half* Bd = Ad + A_H;
#pragma unroll
        for (int u = 0; u < 4; u++) {
            int idx = u * 256 + tid;
            int row = idx >> 3;
            int c8  = (idx & 7) * 8;
            cp16(Ad + row * A_STRIDE_H + c8, A + (size_t)row * lda + kt * BK + c8);
        }
        if (TRANSB) {
#pragma unroll
            for (int u = 0; u < 4; u++) {
                int idx = u * 256 + tid;
                int row = idx >> 4;
                int c   = (idx & 15) * 8;
                cp16(Bd + row * BT_STRIDE_H + c, B + (size_t)(kt * BK + row) * ldb + c);
            }
        } else {
#pragma unroll
            for (int u = 0; u < 4; u++) {
                int idx = u * 256 + tid;
                int row = idx >> 3;
                int c8  = (idx & 7) * 8;
                cp16(Bd + row * A_STRIDE_H + c8, B + (size_t)row * ldb + kt * BK + c8);
            }
        }
        CP_COMMIT();
    };

    load_chunk(0);
    if (kIters > 1) load_chunk(1);

    unsigned a[2][4][4];
    unsigned b[2][4][2];

    const unsigned bstep = TRANSB ? (16u * 272u) : 32u;

    for (int kt = 0; kt < kIters; kt++) {
        if (kt + 1 < kIters) asm volatile("cp.async.wait_group 1;");
        else                 asm volatile("cp.async.wait_group 0;");
        __syncthreads();
        if (kt + 2 < kIters) load_chunk(kt + 2);

        const unsigned stg = sbase + (unsigned)(kt % 3) * STAGE_B;

#pragma unroll
        for (int i = 0; i < 4; i++) LDSM_X4(a[0][i], stg + aoff[i]);
        if (TRANSB) { LDSM_X4T(&b[0][0][0], stg + btoff[0]); LDSM_X4T(&b[0][2][0], stg + btoff[1]); }
        else        { LDSM_X4 (&b[0][0][0], stg + boff[0]);  LDSM_X4 (&b[0][2][0], stg + boff[1]);  }

#pragma unroll
        for (int ks = 0; ks < 4; ks++) {
            const int cu = ks & 1, nb = cu ^ 1;
            if (ks < 3) {
                const unsigned ka = stg + (unsigned)(ks + 1) * 32u;
                const unsigned kb = stg + (unsigned)(ks + 1) * bstep;
                LDSM_X4(a[nb][0], ka + aoff[0]);
#pragma unroll
                for (int i = 0; i < 4; i++) MMA_OP(acc[i][0], a[cu][i], b[cu][0]);
                LDSM_X4(a[nb][1], ka + aoff[1]);
#pragma unroll
                for (int i = 0; i < 4; i++) MMA_OP(acc[i][1], a[cu][i], b[cu][1]);
                LDSM_X4(a[nb][2], ka + aoff[2]);
#pragma unroll
                for (int i = 0; i < 4; i++) MMA_OP(acc[i][2], a[cu][i], b[cu][2]);
                LDSM_X4(a[nb][3], ka + aoff[3]);
                MMA_OP(acc[0][3], a[cu][0], b[cu][3]);
                MMA_OP(acc[1][3], a[cu][1], b[cu][3]);
                if (TRANSB) LDSM_X4T(&b[nb][0][0], kb + btoff[0]);
                else        LDSM_X4 (&b[nb][0][0], kb + boff[0]);
                MMA_OP(acc[2][3], a[cu][2], b[cu][3]);
                if (TRANSB) LDSM_X4T(&b[nb][2][0], kb + btoff[1]);
                else        LDSM_X4 (&b[nb][2][0], kb + boff[1]);
                MMA_OP(acc[3][3], a[cu][3], b[cu][3]);
            } else {
#pragma unroll
                for (int j = 0; j < 4; j++)
#pragma unroll
                    for (int i = 0; i < 4; i++)
                        MMA_OP(acc[i][j], a[cu][i], b[cu][j]);
            }
        }
    }

    const int r0 = l >> 2;
    const int c0 = wn * 32 + 2 * (l & 3);
    if (OUT_MODE == 0) {
        float* Cf = (float*)Cout;
#pragma unroll
        for (int i = 0; i < 4; i++)
#pragma unroll
            for (int j = 0; j < 4; j++) {
                int row = wm * 64 + i * 16 + r0;
                int col = c0 + j * 8;
                *(float2*)(Cf + (size_t)row * ldc + col) =
                    make_float2(acc[i][j][0], acc[i][j][1]);
                *(float2*)(Cf + (size_t)(row + 8) * ldc + col) =
                    make_float2(acc[i][j][2], acc[i][j][3]);
            }
    } else {
        __half* Ch = (__half*)Cout;
#pragma unroll
        for (int i = 0; i < 4; i++)
#pragma unroll
            for (int j = 0; j < 4; j++) {
                int row = wm * 64 + i * 16 + r0;
                int col = c0 + j * 8;
                *(__half2*)(Ch + (size_t)row * ldc + col) =
                    __floats2half2_rn(acc[i][j][0], acc[i][j][1]);
                *(__half2*)(Ch + (size_t)(row + 8) * ldc + col) =
                    __floats2half2_rn(acc[i][j][2], acc[i][j][3]);
            }
    }
}

// ---------------------------------------------------------------------------
// GEMM kernels
// ---------------------------------------------------------------------------
__global__ void __launch_bounds__(256, 2) qkv_gemm()
{
    const int z = blockIdx.z;
    const __half* W   = (z == 0) ? g_wqT : (z == 1) ? g_wkT : g_wvT;
    __half*       out = (z == 0) ? g_qh  : (z == 1) ? g_kh  : g_vh;
    const __half* A = g_xh + (size_t)blockIdx.y * 128 * DIM;
    const __half* B = W    + (size_t)blockIdx.x * 128 * DIM;
    __half*       C = out  + (size_t)blockIdx.y * 128 * DIM + (size_t)blockIdx.x * 128;
    gemm_body<false, 1>(A, B, C, DIM, DIM, DIM, DIM / BK);
}

// Exact lower-triangle grid: 136 tiles/batch, no no-op CTAs.
// Decoded descending in by (uniform work; order irrelevant for scores).
__global__ void __launch_bounds__(256, 2) scores_gemm()
{
    int u = blockIdx.x;           // 0..135
    int by = 15;
    while (u >= by + 1) { u -= (by + 1); by--; }
    const int bx = u;
    const int b = blockIdx.z;
    const __half* A = g_qh + ((size_t)b * SEQ + (size_t)by * 128) * DIM;
    const __half* B = g_kh + ((size_t)b * SEQ + (size_t)bx * 128) * DIM;
    float*        C = g_s  + ((size_t)b * SEQ + (size_t)by * 128) * SEQ + (size_t)bx * 128;
    gemm_body<false, 0>(A, B, C, DIM, DIM, SEQ, DIM / BK);
}

// Longest-first: by = 15 - blockIdx.y so 16-chunk CTAs launch in wave 1.
__global__ void __launch_bounds__(256, 2) pv_gemm(float* __restrict__ out)
{
    const int bx = blockIdx.x, by = 15 - blockIdx.y, b = blockIdx.z;
    const __half* A = g_p  + ((size_t)b * SEQ + (size_t)by * 128) * SEQ;
    const __half* B = g_vh + (size_t)b * SEQ * DIM + (size_t)bx * 128;  // natural V
    float*        C = out  + ((size_t)b * SEQ + (size_t)by * 128) * DIM + (size_t)bx * 128;
    gemm_body<true, 0>(A, B, C, SEQ, DIM, DIM, (by + 1) * 2);  // K to diag
}

// ---------------------------------------------------------------------------
// Data prep
// ---------------------------------------------------------------------------
__global__ void __launch_bounds__(256) x_to_half(const float* __restrict__ x)
{
    const int N4 = MTOT * DIM / 4;
    for (int i = blockIdx.x * blockDim.x + threadIdx.x; i < N4;
         i += gridDim.x * blockDim.x) {
        float4 v = ((const float4*)x)[i];
        __half2* dst = (__half2*)g_xh + 2 * i;
        dst[0] = __floats2half2_rn(v.x, v.y);
        dst[1] = __floats2half2_rn(v.z, v.w);
    }
}

// W [DIN][DOUT] -> W^T [DOUT][DIN] fp16. grid (32,32,3), block (32,8)
__global__ void wT_half(const float* __restrict__ Wq,
                        const float* __restrict__ Wk,
                        const float* __restrict__ Wv)
{
    __shared__ float t[32][33];
    const float* in   = (blockIdx.z == 0) ? Wq : (blockIdx.z == 1) ? Wk : Wv;
    __half*      out  = (blockIdx.z == 0) ? g_wqT : (blockIdx.z == 1) ? g_wkT : g_wvT;
    const int n0 = blockIdx.x * 32, k0 = blockIdx.y * 32;
    const int tx = threadIdx.x, ty = threadIdx.y;
#pragma unroll
    for (int i = 0; i < 32; i += 8)
        t[ty + i][tx] = in[(size_t)(k0 + ty + i) * DIM + n0 + tx];
    __syncthreads();
#pragma unroll
    for (int i = 0; i < 32; i += 8)
        out[(size_t)(n0 + ty + i) * DIM + k0 + tx] = __float2half_rn(t[tx][ty + i]);
}

// ---------------------------------------------------------------------------
// Causal softmax: fp32 scores in, fp16 probs out. Each thread owns 8
// CONTIGUOUS elems: 2x float4 loads, one 16B store. Unpredicated loads are
// safe (g_s memory is deterministic & finite); mask j>=L to -inf / 0.
// Writes only [0, ceil(L/128)*128) — all PV ever reads.
// ---------------------------------------------------------------------------
__global__ void __launch_bounds__(256) softmax_causal()
{
    __shared__ float red[256];
    const int row = blockIdx.x;
    const int b = row >> 11;
    const int i = row & (SEQ - 1);
    const float* srow = g_s + ((size_t)b * SEQ + i) * SEQ;
    __half*      prow = g_p + ((size_t)b * SEQ + i) * SEQ;
    const int L = i + 1;
    const int Lpad = (L + 127) & ~127;
    const int tid = threadIdx.x;
    const int j0 = tid * 8;
    const bool active = (j0 < Lpad);

    float v[8];
    float m = -INFINITY;
    if (active) {
        float4 p0 = *(const float4*)(srow + j0);
        float4 p1 = *(const float4*)(srow + j0 + 4);
        v[0] = p0.x; v[1] = p0.y; v[2] = p0.z; v[3] = p0.w;
        v[4] = p1.x; v[5] = p1.y; v[6] = p1.z; v[7] = p1.w;
#pragma unroll
        for (int u = 0; u < 8; u++) {
            v[u] = (j0 + u < L) ? v[u] * 0.03125f : -INFINITY;
            m = fmaxf(m, v[u]);
        }
    }
    red[tid] = m;
    __syncthreads();
#pragma unroll
    for (int s = 128; s > 0; s >>= 1) {
        if (tid < s) red[tid] = fmaxf(red[tid], red[tid + s]);
        __syncthreads();
    }
    m = red[0];
    __syncthreads();

    float e[8];
    float sum = 0.0f;
    if (active) {
#pragma unroll
        for (int u = 0; u < 8; u++) {
            e[u] = (j0 + u < L) ? __expf(v[u] - m) : 0.0f;
            sum += e[u];
        }
    }
    red[tid] = sum;
    __syncthreads();
#pragma unroll
    for (int s = 128; s > 0; s >>= 1) {
        if (tid < s) red[tid] += red[tid + s];
        __syncthreads();
    }
    const float inv = 1.0f / red[0];

    if (active) {
        __half2 h0 = __floats2half2_rn(e[0] * inv, e[1] * inv);
        __half2 h1 = __floats2half2_rn(e[2] * inv, e[3] * inv);
        __half2 h2 = __floats2half2_rn(e[4] * inv, e[5] * inv);
        __half2 h3 = __floats2half2_rn(e[6] * inv, e[7] * inv);
        uint4 pk;
        pk.x = *(unsigned*)&h0; pk.y = *(unsigned*)&h1;
        pk.z = *(unsigned*)&h2; pk.w = *(unsigned*)&h3;
        *(uint4*)(prow + j0) = pk;
    }
}

// ---------------------------------------------------------------------------
extern "C" void kernel_launch(void* const* d_in, const int* in_sizes, int n_in,
                              void* d_out, int out_size)
{
    const float* x  = (const float*)d_in[0];
    const float* Wq = (const float*)d_in[1];
    const float* Wk = (const float*)d_in[2];
    const float* Wv = (const float*)d_in[3];
    float* out = (float*)d_out;

    cudaFuncSetAttribute(qkv_gemm,    cudaFuncAttributeMaxDynamicSharedMemorySize, SMEM_DYN);
    cudaFuncSetAttribute(scores_gemm, cudaFuncAttributeMaxDynamicSharedMemorySize, SMEM_DYN);
    cudaFuncSetAttribute(pv_gemm,     cudaFuncAttributeMaxDynamicSharedMemorySize, SMEM_DYN);

    dim3 gblk(256);
    dim3 tblk(32, 8);

    x_to_half<<<2048, 256>>>(x);
    wT_half<<<dim3(32, 32, 3), tblk>>>(Wq, Wk, Wv);
    qkv_gemm<<<dim3(DIM / 128, MTOT / 128, 3), gblk, SMEM_DYN>>>();
    scores_gemm<<<dim3(136, 1, BATCH), gblk, SMEM_DYN>>>();   // exact triangle
    softmax_causal<<<dim3(MTOT), 256>>>();
    pv_gemm<<<dim3(DIM / 128, SEQ / 128, BATCH), gblk, SMEM_DYN>>>(out);
}